// round 5
// baseline (speedup 1.0000x reference)
#include <cuda_runtime.h>
#include <cstdint>

#define NUM_CLASSES 1000
#define D 512
#define N_MAX 131072
#define EPT 8

// ---------------- scratch (no allocations allowed) ----------------
__device__ int   g_counts[NUM_CLASSES];          // zeroed at load; re-zeroed by pairwise tail
__device__ int   g_cursor[NUM_CLASSES];          // relative cursor, zeroed like g_counts
__device__ int   g_offsets[NUM_CLASSES + 1];
__device__ int   g_sorted[N_MAX];
__device__ float g_centers[NUM_CLASSES * D];
__device__ float g_sq[NUM_CLASSES];
__device__ int   g_minbits = 0x7F800000;         // +inf; re-armed by pairwise tail
__device__ int   g_done    = 0;
__device__ volatile int g_barrier = 0;           // front-kernel grid barrier; reset by tail

// label dtype sniff: if labels are int32, int64-reinterpretation is out of
// [0,1000) almost surely within the first 512 words.
__device__ __forceinline__ int block_is64(const void* labels) {
    __shared__ int s64;
    if (threadIdx.x == 0) s64 = 1;
    __syncthreads();
    int bad = 0;
    for (int i = threadIdx.x; i < 512; i += blockDim.x) {
        long long v = ((const long long*)labels)[i];
        if (v < 0 || v >= NUM_CLASSES) bad = 1;
    }
    if (bad) s64 = 0;
    __syncthreads();
    return s64;
}

__device__ __forceinline__ int load_label(const void* labels, int i, int is64) {
    if (is64) return (int)((const long long*)labels)[i];
    return ((const int*)labels)[i];
}

// K0: fused histogram -> grid barrier -> per-block scan -> scatter.
// Grid is 64 blocks (all resident on 148 SMs), so the spin barrier is safe.
__global__ void __launch_bounds__(256) k_front(const void* labels, int n) {
    int t = threadIdx.x;
    int is64 = block_is64(labels);
    int base = (blockIdx.x * 256 + t) * EPT;

    // phase A: load labels into registers, histogram
    int lab[EPT];
#pragma unroll
    for (int u = 0; u < EPT; u++)
        lab[u] = (base + u < n) ? load_label(labels, base + u, is64) : -1;
#pragma unroll
    for (int u = 0; u < EPT; u++)
        if (lab[u] >= 0) atomicAdd(&g_counts[lab[u]], 1);

    // grid barrier
    __syncthreads();
    if (t == 0) {
        __threadfence();
        atomicAdd((int*)&g_barrier, 1);
        while (g_barrier < (int)gridDim.x) { }
    }
    __syncthreads();
    __threadfence();  // acquire: counts from all blocks now visible

    // phase B: every block computes the same exclusive scan of g_counts in smem
    __shared__ int soff[1024];
    __shared__ int wsum[8];
    int i0 = 4 * t;
    int c0 = (i0 + 0 < NUM_CLASSES) ? g_counts[i0 + 0] : 0;
    int c1 = (i0 + 1 < NUM_CLASSES) ? g_counts[i0 + 1] : 0;
    int c2 = (i0 + 2 < NUM_CLASSES) ? g_counts[i0 + 2] : 0;
    int c3 = (i0 + 3 < NUM_CLASSES) ? g_counts[i0 + 3] : 0;
    int s = c0 + c1 + c2 + c3;
    int lane = t & 31, warp = t >> 5;
    int x = s;
#pragma unroll
    for (int off = 1; off < 32; off <<= 1) {
        int y = __shfl_up_sync(0xFFFFFFFF, x, off);
        if (lane >= off) x += y;
    }
    if (lane == 31) wsum[warp] = x;
    __syncthreads();
    if (t == 0) {
        int run = 0;
#pragma unroll
        for (int w = 0; w < 8; w++) { int v = wsum[w]; wsum[w] = run; run += v; }
    }
    __syncthreads();
    int excl = wsum[warp] + x - s;          // exclusive prefix for this thread's group of 4
    soff[i0 + 0] = excl;
    soff[i0 + 1] = excl + c0;
    soff[i0 + 2] = excl + c0 + c1;
    soff[i0 + 3] = excl + c0 + c1 + c2;
    __syncthreads();

    // publish offsets for classsum (all blocks write identical values)
    for (int i = t; i < NUM_CLASSES; i += 256) g_offsets[i] = soff[i];
    if (t == 0 && blockIdx.x == 0) g_offsets[NUM_CLASSES] = n;

    // phase C: scatter using smem offsets + global relative cursor
    int pos[EPT];
#pragma unroll
    for (int u = 0; u < EPT; u++)
        if (lab[u] >= 0) pos[u] = soff[lab[u]] + atomicAdd(&g_cursor[lab[u]], 1);
#pragma unroll
    for (int u = 0; u < EPT; u++)
        if (lab[u] >= 0) g_sorted[pos[u]] = base + u;
}

// K1: per-class mean; 256 threads, thread t owns columns 2t,2t+1 (float2).
// Row indices via warp-uniform __ldg broadcast -> no smem staging, no barriers.
__global__ void __launch_bounds__(256) k_classsum(const float* __restrict__ f) {
    int c = blockIdx.x;
    int t = threadIdx.x;
    int s = g_offsets[c], e = g_offsets[c + 1];
    int cnt = e - s;
    int col = 2 * t;

    float ax[8], ay[8];
#pragma unroll
    for (int u = 0; u < 8; u++) { ax[u] = 0.f; ay[u] = 0.f; }

    int r = s;
    for (; r + 8 <= e; r += 8) {
        int idx[8];
#pragma unroll
        for (int u = 0; u < 8; u++) idx[u] = __ldg(&g_sorted[r + u]);
#pragma unroll
        for (int u = 0; u < 8; u++) {
            float2 v = *(const float2*)&f[(size_t)idx[u] * D + col];
            ax[u] += v.x; ay[u] += v.y;
        }
    }
    for (; r < e; r++) {
        float2 v = *(const float2*)&f[(size_t)__ldg(&g_sorted[r]) * D + col];
        ax[0] += v.x; ay[0] += v.y;
    }
    float sx = ((ax[0] + ax[1]) + (ax[2] + ax[3])) + ((ax[4] + ax[5]) + (ax[6] + ax[7]));
    float sy = ((ay[0] + ay[1]) + (ay[2] + ay[3])) + ((ay[4] + ay[5]) + (ay[6] + ay[7]));
    float denom = fmaxf((float)cnt, 1.0f);
    float cx = sx / denom, cy = sy / denom;
    g_centers[c * D + col]     = cx;
    g_centers[c * D + col + 1] = cy;

    float v = cx * cx + cy * cy;
#pragma unroll
    for (int off = 16; off > 0; off >>= 1)
        v += __shfl_down_sync(0xFFFFFFFF, v, off);
    __shared__ float ws[8];
    int warp = t >> 5, lane = t & 31;
    if (lane == 0) ws[warp] = v;
    __syncthreads();
    if (t == 0) {
        float w = 0.f;
#pragma unroll
        for (int i = 0; i < 8; i++) w += ws[i];
        g_sq[c] = w;
    }
}

// K2: pairwise min over upper-triangle tiles (R1 layout — empirically best).
// dis = sq[i]+sq[j]-2*dot (diagonal included, filtered by >0, same as reference).
#define PT 64
#define KC 64
#define GRID_PW 16
__global__ void __launch_bounds__(256) k_pairwise(float* __restrict__ out) {
    int bi = blockIdx.x, bj = blockIdx.y;
    int tid = threadIdx.x;

    __shared__ float As[PT][KC + 1];
    __shared__ float Bs[PT][KC + 1];

    if (bj >= bi) {
        int tx = tid & 15;   // j micro index
        int ty = tid >> 4;   // i micro index

        float acc[4][4];
#pragma unroll
        for (int r = 0; r < 4; r++)
#pragma unroll
            for (int s2 = 0; s2 < 4; s2++) acc[r][s2] = 0.f;

        int rowb = tid >> 4;        // 0..15
        int kk   = (tid & 15) * 4;  // 0..60

        for (int k0 = 0; k0 < D; k0 += KC) {
            __syncthreads();
#pragma unroll
            for (int rr = 0; rr < 4; rr++) {
                int row = rowb + rr * 16;
                int gi = bi * PT + row;
                int gj = bj * PT + row;
                float4 av = (gi < NUM_CLASSES)
                    ? *(const float4*)&g_centers[gi * D + k0 + kk]
                    : make_float4(0.f, 0.f, 0.f, 0.f);
                float4 bv = (gj < NUM_CLASSES)
                    ? *(const float4*)&g_centers[gj * D + k0 + kk]
                    : make_float4(0.f, 0.f, 0.f, 0.f);
                As[row][kk] = av.x; As[row][kk + 1] = av.y; As[row][kk + 2] = av.z; As[row][kk + 3] = av.w;
                Bs[row][kk] = bv.x; Bs[row][kk + 1] = bv.y; Bs[row][kk + 2] = bv.z; Bs[row][kk + 3] = bv.w;
            }
            __syncthreads();
#pragma unroll
            for (int k = 0; k < KC; k++) {
                float a0 = As[ty * 4 + 0][k];
                float a1 = As[ty * 4 + 1][k];
                float a2 = As[ty * 4 + 2][k];
                float a3 = As[ty * 4 + 3][k];
                float b0 = Bs[tx * 4 + 0][k];
                float b1 = Bs[tx * 4 + 1][k];
                float b2 = Bs[tx * 4 + 2][k];
                float b3 = Bs[tx * 4 + 3][k];
                acc[0][0] += a0 * b0; acc[0][1] += a0 * b1; acc[0][2] += a0 * b2; acc[0][3] += a0 * b3;
                acc[1][0] += a1 * b0; acc[1][1] += a1 * b1; acc[1][2] += a1 * b2; acc[1][3] += a1 * b3;
                acc[2][0] += a2 * b0; acc[2][1] += a2 * b1; acc[2][2] += a2 * b2; acc[2][3] += a2 * b3;
                acc[3][0] += a3 * b0; acc[3][1] += a3 * b1; acc[3][2] += a3 * b2; acc[3][3] += a3 * b3;
            }
        }

        float lmin = __int_as_float(0x7F800000);
#pragma unroll
        for (int r = 0; r < 4; r++) {
            int gi = bi * PT + ty * 4 + r;
            if (gi >= NUM_CLASSES) continue;
            float sqi = g_sq[gi];
#pragma unroll
            for (int s2 = 0; s2 < 4; s2++) {
                int gj = bj * PT + tx * 4 + s2;
                if (gj >= NUM_CLASSES) continue;
                float dis = sqi + g_sq[gj] - 2.0f * acc[r][s2];
                if (dis > 0.0f) lmin = fminf(lmin, dis);
            }
        }
#pragma unroll
        for (int off = 16; off > 0; off >>= 1)
            lmin = fminf(lmin, __shfl_down_sync(0xFFFFFFFF, lmin, off));
        if ((tid & 31) == 0 && lmin < __int_as_float(0x7F800000))
            atomicMin(&g_minbits, __float_as_int(lmin));
    }

    // tail: final block writes output and resets all state for the next replay
    __shared__ int s_last;
    if (tid == 0) {
        __threadfence();
        int d = atomicAdd(&g_done, 1);
        s_last = (d == GRID_PW * GRID_PW - 1) ? 1 : 0;
    }
    __syncthreads();
    if (s_last) {
        for (int i = tid; i < NUM_CLASSES; i += 256) { g_counts[i] = 0; g_cursor[i] = 0; }
        if (tid == 0) {
            float dmin = __int_as_float(g_minbits);
            out[0] = fmaxf(1.0f - dmin, 0.0f);   // MARGIN_INTER=1, BETA=1
            g_minbits = 0x7F800000;
            g_done = 0;
            g_barrier = 0;
        }
    }
}

extern "C" void kernel_launch(void* const* d_in, const int* in_sizes, int n_in,
                              void* d_out, int out_size) {
    const float* features = (const float*)d_in[0];
    const void*  labels   = d_in[1];
    int n = in_sizes[1];
    float* out = (float*)d_out;

    int nb = (n + 256 * EPT - 1) / (256 * EPT);   // 64 for n=131072 (all-resident)
    k_front<<<nb, 256>>>(labels, n);
    k_classsum<<<NUM_CLASSES, 256>>>(features);
    dim3 pg(GRID_PW, GRID_PW);
    k_pairwise<<<pg, 256>>>(out);
}

// round 7
// speedup vs baseline: 1.2103x; 1.2103x over previous
#include <cuda_runtime.h>
#include <cstdint>

#define NUM_CLASSES 1000
#define D 512
#define N_MAX 131072
#define EPT 4

// ---------------- scratch (no allocations allowed) ----------------
__device__ int   g_counts[NUM_CLASSES];          // zeroed at load; re-zeroed by pairwise tail
__device__ int   g_cursor[NUM_CLASSES];          // relative cursor, zeroed like g_counts
__device__ int   g_offsets[NUM_CLASSES + 1];
__device__ int   g_sorted[N_MAX];
__device__ float g_centers[NUM_CLASSES * D];
__device__ float g_sq[NUM_CLASSES];
__device__ int   g_minbits = 0x7F800000;         // +inf; re-armed by pairwise tail
__device__ int   g_done    = 0;

// label dtype sniff: if labels are int32, int64-reinterpretation is out of
// [0,1000) almost surely within the first 512 words.
__device__ __forceinline__ int block_is64(const void* labels) {
    __shared__ int s64;
    if (threadIdx.x == 0) s64 = 1;
    __syncthreads();
    int bad = 0;
    for (int i = threadIdx.x; i < 512; i += blockDim.x) {
        long long v = ((const long long*)labels)[i];
        if (v < 0 || v >= NUM_CLASSES) bad = 1;
    }
    if (bad) s64 = 0;
    __syncthreads();
    return s64;
}

__device__ __forceinline__ int load_label(const void* labels, int i, int is64) {
    if (is64) return (int)((const long long*)labels)[i];
    return ((const int*)labels)[i];
}

// K0: histogram, EPT labels per thread (batched atomics), 128 blocks
__global__ void __launch_bounds__(256) k_hist(const void* labels, int n) {
    int is64 = block_is64(labels);
    int base = (blockIdx.x * blockDim.x + threadIdx.x) * EPT;
#pragma unroll
    for (int u = 0; u < EPT; u++) {
        int i = base + u;
        if (i < n) atomicAdd(&g_counts[load_label(labels, i, is64)], 1);
    }
}

// K1: per-block redundant scan of g_counts into smem, then scatter.
// (hist->scatter kernel boundary orders the counts; no grid barrier needed)
__global__ void __launch_bounds__(256) k_scatter(const void* labels, int n) {
    int t = threadIdx.x;
    int is64 = block_is64(labels);

    // exclusive scan of 1000 counts into smem (every block computes the same)
    __shared__ int soff[1024];
    __shared__ int wsum[8];
    int i0 = 4 * t;
    int c0 = (i0 + 0 < NUM_CLASSES) ? g_counts[i0 + 0] : 0;
    int c1 = (i0 + 1 < NUM_CLASSES) ? g_counts[i0 + 1] : 0;
    int c2 = (i0 + 2 < NUM_CLASSES) ? g_counts[i0 + 2] : 0;
    int c3 = (i0 + 3 < NUM_CLASSES) ? g_counts[i0 + 3] : 0;
    int sgrp = c0 + c1 + c2 + c3;
    int lane = t & 31, warp = t >> 5;
    int x = sgrp;
#pragma unroll
    for (int off = 1; off < 32; off <<= 1) {
        int y = __shfl_up_sync(0xFFFFFFFF, x, off);
        if (lane >= off) x += y;
    }
    if (lane == 31) wsum[warp] = x;
    __syncthreads();
    if (t == 0) {
        int run = 0;
#pragma unroll
        for (int w = 0; w < 8; w++) { int v = wsum[w]; wsum[w] = run; run += v; }
    }
    __syncthreads();
    int excl = wsum[warp] + x - sgrp;
    soff[i0 + 0] = excl;
    soff[i0 + 1] = excl + c0;
    soff[i0 + 2] = excl + c0 + c1;
    soff[i0 + 3] = excl + c0 + c1 + c2;
    __syncthreads();

    // publish offsets for classsum (all blocks write identical values)
    for (int i = t; i < NUM_CLASSES; i += 256) g_offsets[i] = soff[i];
    if (t == 0 && blockIdx.x == 0) g_offsets[NUM_CLASSES] = n;

    // scatter with batched atomics
    int base = (blockIdx.x * 256 + t) * EPT;
    int lab[EPT], pos[EPT];
#pragma unroll
    for (int u = 0; u < EPT; u++)
        lab[u] = (base + u < n) ? load_label(labels, base + u, is64) : -1;
#pragma unroll
    for (int u = 0; u < EPT; u++)
        if (lab[u] >= 0) pos[u] = soff[lab[u]] + atomicAdd(&g_cursor[lab[u]], 1);
#pragma unroll
    for (int u = 0; u < EPT; u++)
        if (lab[u] >= 0) g_sorted[pos[u]] = base + u;
}

// K2: per-class mean (R3's measured-best config: 256 threads, float2 columns,
// smem-staged indices, 8-row unroll).
__global__ void __launch_bounds__(256) k_classsum(const float* __restrict__ f) {
    int c = blockIdx.x;
    int t = threadIdx.x;
    int s = g_offsets[c], e = g_offsets[c + 1];
    int cnt = e - s;

    __shared__ int sidx[512];
    float ax[8], ay[8];
#pragma unroll
    for (int u = 0; u < 8; u++) { ax[u] = 0.f; ay[u] = 0.f; }

    for (int base = s; base < e; base += 512) {
        int m = e - base; if (m > 512) m = 512;
        __syncthreads();
        for (int i = t; i < m; i += 256) sidx[i] = g_sorted[base + i];
        __syncthreads();
        int r = 0;
        for (; r + 8 <= m; r += 8) {
#pragma unroll
            for (int u = 0; u < 8; u++) {
                float2 v = *(const float2*)&f[(size_t)sidx[r + u] * D + 2 * t];
                ax[u] += v.x; ay[u] += v.y;
            }
        }
        for (; r < m; r++) {
            float2 v = *(const float2*)&f[(size_t)sidx[r] * D + 2 * t];
            ax[0] += v.x; ay[0] += v.y;
        }
    }
    float sx = ((ax[0] + ax[1]) + (ax[2] + ax[3])) + ((ax[4] + ax[5]) + (ax[6] + ax[7]));
    float sy = ((ay[0] + ay[1]) + (ay[2] + ay[3])) + ((ay[4] + ay[5]) + (ay[6] + ay[7]));
    float denom = fmaxf((float)cnt, 1.0f);
    float cx = sx / denom, cy = sy / denom;
    g_centers[c * D + 2 * t]     = cx;
    g_centers[c * D + 2 * t + 1] = cy;

    float v = cx * cx + cy * cy;
#pragma unroll
    for (int off = 16; off > 0; off >>= 1)
        v += __shfl_down_sync(0xFFFFFFFF, v, off);
    __shared__ float ws[8];
    int warp = t >> 5, lane = t & 31;
    if (lane == 0) ws[warp] = v;
    __syncthreads();
    if (t == 0) {
        float w = 0.f;
#pragma unroll
        for (int i = 0; i < 8; i++) w += ws[i];
        g_sq[c] = w;
    }
}

// K3: pairwise min over upper-triangle tiles (R1 layout — empirically best).
// dis = sq[i]+sq[j]-2*dot (diagonal included, filtered by >0, same as reference).
#define PT 64
#define KC 64
#define GRID_PW 16
__global__ void __launch_bounds__(256) k_pairwise(float* __restrict__ out) {
    int bi = blockIdx.x, bj = blockIdx.y;
    int tid = threadIdx.x;

    __shared__ float As[PT][KC + 1];
    __shared__ float Bs[PT][KC + 1];

    if (bj >= bi) {
        int tx = tid & 15;   // j micro index
        int ty = tid >> 4;   // i micro index

        float acc[4][4];
#pragma unroll
        for (int r = 0; r < 4; r++)
#pragma unroll
            for (int s2 = 0; s2 < 4; s2++) acc[r][s2] = 0.f;

        int rowb = tid >> 4;        // 0..15
        int kk   = (tid & 15) * 4;  // 0..60

        for (int k0 = 0; k0 < D; k0 += KC) {
            __syncthreads();
#pragma unroll
            for (int rr = 0; rr < 4; rr++) {
                int row = rowb + rr * 16;
                int gi = bi * PT + row;
                int gj = bj * PT + row;
                float4 av = (gi < NUM_CLASSES)
                    ? *(const float4*)&g_centers[gi * D + k0 + kk]
                    : make_float4(0.f, 0.f, 0.f, 0.f);
                float4 bv = (gj < NUM_CLASSES)
                    ? *(const float4*)&g_centers[gj * D + k0 + kk]
                    : make_float4(0.f, 0.f, 0.f, 0.f);
                As[row][kk] = av.x; As[row][kk + 1] = av.y; As[row][kk + 2] = av.z; As[row][kk + 3] = av.w;
                Bs[row][kk] = bv.x; Bs[row][kk + 1] = bv.y; Bs[row][kk + 2] = bv.z; Bs[row][kk + 3] = bv.w;
            }
            __syncthreads();
#pragma unroll
            for (int k = 0; k < KC; k++) {
                float a0 = As[ty * 4 + 0][k];
                float a1 = As[ty * 4 + 1][k];
                float a2 = As[ty * 4 + 2][k];
                float a3 = As[ty * 4 + 3][k];
                float b0 = Bs[tx * 4 + 0][k];
                float b1 = Bs[tx * 4 + 1][k];
                float b2 = Bs[tx * 4 + 2][k];
                float b3 = Bs[tx * 4 + 3][k];
                acc[0][0] += a0 * b0; acc[0][1] += a0 * b1; acc[0][2] += a0 * b2; acc[0][3] += a0 * b3;
                acc[1][0] += a1 * b0; acc[1][1] += a1 * b1; acc[1][2] += a1 * b2; acc[1][3] += a1 * b3;
                acc[2][0] += a2 * b0; acc[2][1] += a2 * b1; acc[2][2] += a2 * b2; acc[2][3] += a2 * b3;
                acc[3][0] += a3 * b0; acc[3][1] += a3 * b1; acc[3][2] += a3 * b2; acc[3][3] += a3 * b3;
            }
        }

        float lmin = __int_as_float(0x7F800000);
#pragma unroll
        for (int r = 0; r < 4; r++) {
            int gi = bi * PT + ty * 4 + r;
            if (gi >= NUM_CLASSES) continue;
            float sqi = g_sq[gi];
#pragma unroll
            for (int s2 = 0; s2 < 4; s2++) {
                int gj = bj * PT + tx * 4 + s2;
                if (gj >= NUM_CLASSES) continue;
                float dis = sqi + g_sq[gj] - 2.0f * acc[r][s2];
                if (dis > 0.0f) lmin = fminf(lmin, dis);
            }
        }
#pragma unroll
        for (int off = 16; off > 0; off >>= 1)
            lmin = fminf(lmin, __shfl_down_sync(0xFFFFFFFF, lmin, off));
        if ((tid & 31) == 0 && lmin < __int_as_float(0x7F800000))
            atomicMin(&g_minbits, __float_as_int(lmin));
    }

    // tail: final block writes output and resets state for the next replay
    __shared__ int s_last;
    if (tid == 0) {
        __threadfence();
        int d = atomicAdd(&g_done, 1);
        s_last = (d == GRID_PW * GRID_PW - 1) ? 1 : 0;
    }
    __syncthreads();
    if (s_last) {
        for (int i = tid; i < NUM_CLASSES; i += 256) { g_counts[i] = 0; g_cursor[i] = 0; }
        if (tid == 0) {
            float dmin = __int_as_float(g_minbits);
            out[0] = fmaxf(1.0f - dmin, 0.0f);   // MARGIN_INTER=1, BETA=1
            g_minbits = 0x7F800000;
            g_done = 0;
        }
    }
}

extern "C" void kernel_launch(void* const* d_in, const int* in_sizes, int n_in,
                              void* d_out, int out_size) {
    const float* features = (const float*)d_in[0];
    const void*  labels   = d_in[1];
    int n = in_sizes[1];
    float* out = (float*)d_out;

    int nb = (n + 256 * EPT - 1) / (256 * EPT);   // 128 blocks for n=131072
    k_hist<<<nb, 256>>>(labels, n);
    k_scatter<<<nb, 256>>>(labels, n);
    k_classsum<<<NUM_CLASSES, 256>>>(features);
    dim3 pg(GRID_PW, GRID_PW);
    k_pairwise<<<pg, 256>>>(out);
}